// round 11
// baseline (speedup 1.0000x reference)
#include <cuda_runtime.h>
#include <math.h>

#define DIM   128
#define KC    8
#define NMAX  50000
#define EMAX  1600000
#define XCAP  44            // max edges in register cache per row (multiple of 4)
#define T4MAX (XCAP / 4)    // 11 float4 per thread
#define PSTR  52            // pbuf row stride (20c mod 32 bijective -> conflict-free)
#define NQ    ((XCAP + 15) / 16)
#define NBLK  888           // persistent grid: 148 SMs x 6 blocks
#define FULLM 0xFFFFFFFFu

__device__ __align__(256) float g_xn[(size_t)NMAX * DIM];   // normalized x (25.6 MB)
__device__ __align__(256) float g_pbuf[(size_t)EMAX * KC];  // fallback p scratch
__device__ int g_rs[NMAX + 1];                              // row CSR offsets

// ---------------------------------------------------------------------------
__global__ void knorm(const float* __restrict__ x, int ncap) {
    int i = blockIdx.x * blockDim.x + threadIdx.x;
    if (i >= ncap) return;
    const float4* src = ((const float4*)x) + (size_t)i * 4;
    float4 a = src[0], b = src[1], c = src[2], d = src[3];
    float s = a.x*a.x + a.y*a.y + a.z*a.z + a.w*a.w
            + b.x*b.x + b.y*b.y + b.z*b.z + b.w*b.w
            + c.x*c.x + c.y*c.y + c.z*c.z + c.w*c.w
            + d.x*d.x + d.y*d.y + d.z*d.z + d.w*d.w;
    float inv = 1.0f / fmaxf(sqrtf(s), 1e-12f);
    a.x*=inv; a.y*=inv; a.z*=inv; a.w*=inv;
    b.x*=inv; b.y*=inv; b.z*=inv; b.w*=inv;
    c.x*=inv; c.y*=inv; c.z*=inv; c.w*=inv;
    d.x*=inv; d.y*=inv; d.z*=inv; d.w*=inv;
    float4* dst = ((float4*)g_xn) + (size_t)i * 4;
    dst[0]=a; dst[1]=b; dst[2]=c; dst[3]=d;
}

// ---------------------------------------------------------------------------
__global__ void krows(const int* __restrict__ row_idx, int n, int E) {
    int r = blockIdx.x * blockDim.x + threadIdx.x;
    if (r > n) return;
    if (r == n) { g_rs[n] = E; return; }
    int lo = 0, hi = E;
    while (lo < hi) {
        int mid = (lo + hi) >> 1;
        if (row_idx[mid] < r) lo = mid + 1; else hi = mid;
    }
    g_rs[r] = lo;
}

__device__ __forceinline__ float dot4(float4 a, float4 b) {
    return a.x*b.x + a.y*b.y + a.z*b.z + a.w*b.w;
}

// ---------------------------------------------------------------------------
// PERSISTENT kernel: 888 blocks of 128 threads; each block grid-strides over
// rows (~56 rows/block), 3 routing iterations fused per row.
// Per-row body identical to the register-resident design:
//   thread (w,l) holds x[col[e]] float4 #l for edges e = w + 4i in registers.
//   Pass A: dot4 + 2-SHFL butterfly over the 4 lanes of capsule cgrp = l>>2.
//   Softmax: thread t -> capsule t>>4, strip t&15; no max subtraction
//            (|p| <= sum ppr <= XCAP -> exp can't overflow fp32).
//   Pass B: register FMAs; cross-warp reduce via red4.
// ---------------------------------------------------------------------------
__global__ void __launch_bounds__(128, 6) kmain(
    const float* __restrict__ pprg,
    const int* __restrict__ colg,
    float* __restrict__ out, int n, int E)
{
    extern __shared__ float smem[];
    float*  pbuf   = smem;                            // KC*PSTR (1664 B)
    float*  ppr_sh = pbuf + KC*PSTR;                  // XCAP
    float*  ssv    = ppr_sh + XCAP;                   // 8
    float4* red4   = (float4*)(ssv + KC);             // 128 float4 (2048 B)

    const int t = threadIdx.x;
    const int w = t >> 5, l = t & 31;
    const int cgrp = l >> 2;                // capsule of this lane's dims
    const int k16 = t >> 4, j16 = t & 15;   // softmax mapping

    for (int r = blockIdx.x; r < n; r += NBLK) {

    const int s = g_rs[r];
    int cnt = g_rs[r + 1] - s;
    cnt = max(0, min(cnt, E));
    const int cnt4 = (cnt + 3) & ~3;
    const int T4 = cnt4 >> 2;

    if (cnt <= XCAP) {
        // =================== REGISTER-CACHED PATH ===================
        int* col_sh = (int*)pbuf;     // union: col only needed during staging
        for (int i = t; i < cnt4; i += 128) {
            col_sh[i] = (i < cnt) ? colg[s + i] : 0;
            ppr_sh[i] = (i < cnt) ? pprg[s + i] : 0.f;
        }
        __syncthreads();

        // gather x into registers (up to 11 independent loads), fused u-init
        float4 xv[T4MAX];
        float4 u4 = make_float4(0.f,0.f,0.f,0.f);
        #pragma unroll
        for (int i = 0; i < T4MAX; i++) {
            int e = w + (i << 2);
            float4 v = make_float4(0.f,0.f,0.f,0.f);
            float pe = 0.f;
            if (i < T4) {
                if (e < cnt) v = ((const float4*)(g_xn + (size_t)col_sh[e]*DIM))[l];
                pe = ppr_sh[e];
            }
            xv[i] = v;
            u4.x += v.x*pe; u4.y += v.y*pe; u4.z += v.z*pe; u4.w += v.w*pe;
        }
        red4[t] = u4;
        __syncthreads();
        {   // cross-warp reduce: every thread gets full dims 4l..4l+4 of u
            float4 a0 = red4[l], a1 = red4[32+l], a2 = red4[64+l], a3 = red4[96+l];
            u4.x = a0.x+a1.x+a2.x+a3.x; u4.y = a0.y+a1.y+a2.y+a3.y;
            u4.z = a0.z+a1.z+a2.z+a3.z; u4.w = a0.w+a1.w+a2.w+a3.w;
        }

        #pragma unroll
        for (int it = 0; it < 3; it++) {
            __syncthreads();   // pbuf reuse: prior staging/softmax reads done

            // ---- Pass A: register dot + 4-lane butterfly ----
            #pragma unroll
            for (int i = 0; i < T4MAX; i++) {
                if (i < T4) {
                    int e = w + (i << 2);
                    float d = dot4(u4, xv[i]);
                    d += __shfl_xor_sync(FULLM, d, 1);
                    d += __shfl_xor_sync(FULLM, d, 2);
                    if ((l & 3) == 0) pbuf[cgrp*PSTR + e] = d;
                }
            }
            __syncthreads();                           // B1

            // ---- softmax (no max) + blend + second exp ----
            float pv[NQ];
            float S = 0.f;
            #pragma unroll
            for (int q = 0; q < NQ; q++) {
                int e = j16 + q*16;
                float v = 0.f;
                if (e < cnt) v = __expf(pbuf[k16*PSTR + e]);
                pv[q] = v; S += v;
            }
            S += __shfl_xor_sync(FULLM, S, 1);
            S += __shfl_xor_sync(FULLM, S, 2);
            S += __shfl_xor_sync(FULLM, S, 4);
            S += __shfl_xor_sync(FULLM, S, 8);
            float Sinv = 1.f / fmaxf(S, 1e-30f);
            float S2 = 0.f;
            #pragma unroll
            for (int q = 0; q < NQ; q++) {
                int e = j16 + q*16;
                if (e < cnt) {
                    float b = 0.5f * pv[q] * Sinv + 0.5f * ppr_sh[e];
                    float v2 = __expf(b);
                    pbuf[k16*PSTR + e] = v2;
                    S2 += v2;
                }
            }
            S2 += __shfl_xor_sync(FULLM, S2, 1);
            S2 += __shfl_xor_sync(FULLM, S2, 2);
            S2 += __shfl_xor_sync(FULLM, S2, 4);
            S2 += __shfl_xor_sync(FULLM, S2, 8);
            if (j16 == 0) ssv[k16] = 1.f / fmaxf(S2, 1e-30f);
            __syncthreads();                           // B2

            // ---- Pass B: register FMAs (pad edges: xv = 0) ----
            float4 acc = make_float4(0.f,0.f,0.f,0.f);
            #pragma unroll
            for (int i = 0; i < T4MAX; i++) {
                if (i < T4) {
                    int e = w + (i << 2);
                    float pw = pbuf[cgrp*PSTR + e];
                    acc.x += xv[i].x*pw; acc.y += xv[i].y*pw;
                    acc.z += xv[i].z*pw; acc.w += xv[i].w*pw;
                }
            }
            red4[t] = acc;
            __syncthreads();                           // B3

            float s2i = ssv[cgrp];
            float4 a0 = red4[l], a1 = red4[32+l], a2 = red4[64+l], a3 = red4[96+l];
            float4 un;
            un.x = (a0.x+a1.x+a2.x+a3.x) * s2i;
            un.y = (a0.y+a1.y+a2.y+a3.y) * s2i;
            un.z = (a0.z+a1.z+a2.z+a3.z) * s2i;
            un.w = (a0.w+a1.w+a2.w+a3.w) * s2i;

            if (it < 2) {
                float sq = un.x*un.x + un.y*un.y + un.z*un.z + un.w*un.w;
                sq += __shfl_xor_sync(FULLM, sq, 1);
                sq += __shfl_xor_sync(FULLM, sq, 2);
                float inv = 1.f / fmaxf(sqrtf(sq), 1e-12f);
                u4.x = un.x*inv; u4.y = un.y*inv; u4.z = un.z*inv; u4.w = un.w*inv;
            } else if (w == 0) {
                ((float4*)(out + (size_t)r * DIM))[l] = un;
            }
        }
        __syncthreads();   // end of row: red4/ssv reads done before next staging
    } else {
        // =================== FALLBACK PATH (~2% of rows) ===================
        float* pb_g = g_pbuf + (size_t)s * KC;   // [k*cnt + e]

        float4 u4 = make_float4(0.f,0.f,0.f,0.f);
        for (int e = w; e < cnt; e += 4) {
            float4 xv = ((const float4*)(g_xn + (size_t)colg[s+e]*DIM))[l];
            float pe = pprg[s + e];
            u4.x += xv.x*pe; u4.y += xv.y*pe; u4.z += xv.z*pe; u4.w += xv.w*pe;
        }
        red4[t] = u4;
        __syncthreads();
        {
            float4 a0 = red4[l], a1 = red4[32+l], a2 = red4[64+l], a3 = red4[96+l];
            u4.x = a0.x+a1.x+a2.x+a3.x; u4.y = a0.y+a1.y+a2.y+a3.y;
            u4.z = a0.z+a1.z+a2.z+a3.z; u4.w = a0.w+a1.w+a2.w+a3.w;
        }

        #pragma unroll
        for (int it = 0; it < 3; it++) {
            for (int e = w; e < cnt; e += 4) {
                float4 xv = ((const float4*)(g_xn + (size_t)colg[s+e]*DIM))[l];
                float d = u4.x*xv.x + u4.y*xv.y + u4.z*xv.z + u4.w*xv.w;
                d += __shfl_xor_sync(FULLM, d, 1);
                d += __shfl_xor_sync(FULLM, d, 2);
                if ((l & 3) == 0) pb_g[cgrp*cnt + e] = d;
            }
            __syncthreads();

            float m = -1e30f;
            for (int e = j16; e < cnt; e += 16)
                m = fmaxf(m, pb_g[k16*cnt + e]);
            m = fmaxf(m, __shfl_xor_sync(FULLM, m, 1));
            m = fmaxf(m, __shfl_xor_sync(FULLM, m, 2));
            m = fmaxf(m, __shfl_xor_sync(FULLM, m, 4));
            m = fmaxf(m, __shfl_xor_sync(FULLM, m, 8));
            float S = 0.f;
            for (int e = j16; e < cnt; e += 16) {
                float v = __expf(pb_g[k16*cnt + e] - m);
                pb_g[k16*cnt + e] = v; S += v;
            }
            S += __shfl_xor_sync(FULLM, S, 1);
            S += __shfl_xor_sync(FULLM, S, 2);
            S += __shfl_xor_sync(FULLM, S, 4);
            S += __shfl_xor_sync(FULLM, S, 8);
            float Sinv = 1.f / fmaxf(S, 1e-30f);
            float S2 = 0.f;
            for (int e = j16; e < cnt; e += 16) {
                float b = 0.5f * pb_g[k16*cnt + e] * Sinv + 0.5f * pprg[s + e];
                float v2 = __expf(b);
                pb_g[k16*cnt + e] = v2; S2 += v2;
            }
            S2 += __shfl_xor_sync(FULLM, S2, 1);
            S2 += __shfl_xor_sync(FULLM, S2, 2);
            S2 += __shfl_xor_sync(FULLM, S2, 4);
            S2 += __shfl_xor_sync(FULLM, S2, 8);
            if (j16 == 0) ssv[k16] = 1.f / fmaxf(S2, 1e-30f);
            __syncthreads();

            float4 acc = make_float4(0.f,0.f,0.f,0.f);
            for (int e = w; e < cnt; e += 4) {
                float4 xv = ((const float4*)(g_xn + (size_t)colg[s+e]*DIM))[l];
                float pw = pb_g[cgrp*cnt + e];
                acc.x += xv.x*pw; acc.y += xv.y*pw;
                acc.z += xv.z*pw; acc.w += xv.w*pw;
            }
            red4[t] = acc;
            __syncthreads();
            float s2i = ssv[cgrp];
            float4 a0 = red4[l], a1 = red4[32+l], a2 = red4[64+l], a3 = red4[96+l];
            float4 un;
            un.x = (a0.x+a1.x+a2.x+a3.x) * s2i;
            un.y = (a0.y+a1.y+a2.y+a3.y) * s2i;
            un.z = (a0.z+a1.z+a2.z+a3.z) * s2i;
            un.w = (a0.w+a1.w+a2.w+a3.w) * s2i;

            if (it < 2) {
                float sq = un.x*un.x + un.y*un.y + un.z*un.z + un.w*un.w;
                sq += __shfl_xor_sync(FULLM, sq, 1);
                sq += __shfl_xor_sync(FULLM, sq, 2);
                float inv = 1.f / fmaxf(sqrtf(sq), 1e-12f);
                u4.x = un.x*inv; u4.y = un.y*inv; u4.z = un.z*inv; u4.w = un.w*inv;
            } else if (w == 0) {
                ((float4*)(out + (size_t)r * DIM))[l] = un;
            }
            __syncthreads();   // pb_g/red4 reuse next iteration or next row
        }
    }

    }  // row loop
}

// ---------------------------------------------------------------------------
extern "C" void kernel_launch(void* const* d_in, const int* in_sizes, int n_in,
                              void* d_out, int out_size)
{
    const float* x    = (const float*)d_in[0];
    const float* ppr  = (const float*)d_in[1];
    const int*   row  = (const int*)  d_in[2];
    const int*   col  = (const int*)  d_in[3];
    float* out = (float*)d_out;

    int n = in_sizes[0] / DIM;
    if (n > NMAX) n = NMAX;
    int E = in_sizes[1];
    if (E > EMAX) E = EMAX;
    if (n <= 0) return;

    const int ncap = n * KC;
    knorm<<<(ncap + 255) / 256, 256>>>(x, ncap);
    krows<<<(n + 1 + 255) / 256, 256>>>(row, n, E);

    // smem floats: pbuf 8*52 + ppr 44 + ssv 8 + red4 512  = 980 -> 3920 B
    const size_t SMEM = (size_t)(KC*PSTR + XCAP + KC + DIM*4) * sizeof(float);
    int grid = n < NBLK ? n : NBLK;
    kmain<<<grid, 128, SMEM>>>(ppr, col, out, n, E);
}